// round 14
// baseline (speedup 1.0000x reference)
#include <cuda_runtime.h>
#include <math.h>
#include <stdint.h>

#define H 2048
#define HH (H*H)
#define TW 64                  // tile width (cols)
#define TH 8                   // tile height (rows)
#define IN_W 76                // input smem stride: cols c0-4 .. c0+71 (19 float4)
#define IN_H 12                // rows r0-2 .. r0+9
#define IN_HW (IN_H * IN_W)
#define YW 72                  // y smem stride: sc = (gy-c0) + 3
#define YH 10                  // y rows: gyr = r0-1+ly, ly 0..9
#define TILES_X (H / TW)       // 32
#define NTILES ((H / TH) * TILES_X)   // 8192
#define GRID 1332              // 148 SMs * 9 CTAs

__device__ __forceinline__ int dscalar(const int* p, int def) {
    return p ? p[0] : def;
}

__device__ __forceinline__ void cp_async16(uint32_t dst_smem, const void* src, int src_bytes) {
    asm volatile("cp.async.cg.shared.global [%0], [%1], 16, %2;\n"
                 :: "r"(dst_smem), "l"(src), "r"(src_bytes));
}
__device__ __forceinline__ void cp_async_commit() {
    asm volatile("cp.async.commit_group;\n");
}
__device__ __forceinline__ void cp_async_wait1() {
    asm volatile("cp.async.wait_group 1;\n" ::: "memory");
}

__global__ __launch_bounds__(128, 9)
void pgonet_main(const float* __restrict__ ref_speed,
                 const float* __restrict__ batch,
                 const float* __restrict__ x_tt,
                 const float* __restrict__ x_t,
                 const float* __restrict__ conv_v,
                 const float* __restrict__ conv_g,
                 const float* __restrict__ conv_b,
                 const float* __restrict__ ref_sol,
                 const int*   __restrict__ loc_x,
                 const int*   __restrict__ loc_y,
                 const int* p_bsize, const int* p_id,
                 const int* p_flag, const int* p_flag_num,
                 float* __restrict__ out, int P)
{
    __shared__ float s_buf[2][3 * IN_HW];   // double-buffered inputs
    __shared__ float s_y[YH * YW];
    __shared__ float4 s_W4[9];
    __shared__ float s_b;

    const int tx = threadIdx.x & 15;
    const int ty = threadIdx.x >> 4;
    const int tid = threadIdx.x;

    const int bsize = dscalar(p_bsize, 10);
    const int ntb   = dscalar(p_flag, 1) - 1;
    const int step  = dscalar(p_flag_num, 1) - 1;
    const int i0    = ntb * bsize + step;
    const float* __restrict__ xtt_g = batch + (size_t)i0 * HH;
    const float* __restrict__ xt_g  = batch + (size_t)(i0 + 1) * HH;

    uint32_t s_buf_u32;
    {
        uint32_t a;
        asm("{ .reg .u64 t; cvta.to.shared.u64 t, %1; cvt.u32.u64 %0, t; }"
            : "=r"(a) : "l"(&s_buf[0][0]));
        s_buf_u32 = a;
    }

    // stage one tile's inputs into buffer pb
    auto stage = [&](int tile, int pb) {
        int r0 = (tile >> 5) * TH;
        int c0 = (tile & 31) * TW;
        #pragma unroll
        for (int it = 0; it < 6; it++) {
            int idx = tid + it * 128;
            if (idx < 3 * IN_H * 19) {
                int ch = idx / (IN_H * 19);
                int k  = idx - ch * (IN_H * 19);
                int lr = k / 19, lq = k - lr * 19;
                int gr = r0 - 2 + lr;
                int gc = c0 - 4 + 4 * lq;
                bool ok = (gr >= 0) && (gr < H) && (gc >= 0) && (gc + 3 < H);
                const float* p = (ch == 0) ? xtt_g : ((ch == 1) ? xt_g : ref_speed);
                const float* src = p + (ok ? ((size_t)gr * H + gc) : 0);
                uint32_t dst = s_buf_u32
                    + 4u * (pb * 3 * IN_HW + ch * IN_HW + lr * IN_W + 4 * lq);
                cp_async16(dst, src, ok ? 16 : 0);
            }
        }
    };

    if (tid == 0) {
        float ss = 0.f;
        #pragma unroll
        for (int i = 0; i < 27; i++) { float v = conv_v[i]; ss += v * v; }
        float scale = conv_g[0] / sqrtf(ss);
        #pragma unroll
        for (int i = 0; i < 9; i++)
            s_W4[i] = make_float4(conv_v[3 * i] * scale,
                                  conv_v[3 * i + 1] * scale,
                                  conv_v[3 * i + 2] * scale, 0.f);
        s_b = conv_b[0];
    }

    int tile = blockIdx.x;
    int pb = 0;
    if (tile < NTILES) stage(tile, 0);
    cp_async_commit();

    #pragma unroll 1
    for (; tile < NTILES; tile += GRID) {
        int nxt = tile + GRID;
        if (nxt < NTILES) stage(nxt, pb ^ 1);
        cp_async_commit();          // group for nxt (possibly empty)
        cp_async_wait1();           // current tile's data resident
        __syncthreads();

        const float* s_in  = &s_buf[pb][0];
        const float* s_xtt = s_in;
        const float* s_xt  = s_in + IN_HW;
        const float* s_sp  = s_in + 2 * IN_HW;
        const int r0 = (tile >> 5) * TH;
        const int c0 = (tile & 31) * TW;

        // ==== phase B: conv on warps 0-2 (90 strips); copies on warp 3 ====
        if (tid < 96) {
            if (tid < YH * 9) {
                const float bconv = s_b;
                int ly = tid / 9, q = tid - ly * 9;
                float acc[8];
                #pragma unroll
                for (int k = 0; k < 8; k++) acc[k] = bconv;
                #pragma unroll
                for (int ch = 0; ch < 3; ch++) {
                    #pragma unroll
                    for (int kh = 0; kh < 3; kh++) {
                        const float4* rp = reinterpret_cast<const float4*>(
                            s_in + ch * IN_HW + (ly + kh) * IN_W + 8 * q);
                        float4 A = rp[0], B = rp[1], C = rp[2];
                        float t[12] = {A.x, A.y, A.z, A.w, B.x, B.y, B.z, B.w,
                                       C.x, C.y, C.z, C.w};
                        float4 w = s_W4[ch * 3 + kh];
                        #pragma unroll
                        for (int k = 0; k < 8; k++) {
                            acc[k] = fmaf(w.x, t[k], acc[k]);
                            acc[k] = fmaf(w.y, t[k + 1], acc[k]);
                            acc[k] = fmaf(w.z, t[k + 2], acc[k]);
                        }
                    }
                }
                float4* yp = reinterpret_cast<float4*>(s_y + ly * YW + 8 * q);
                yp[0] = make_float4(acc[0], acc[1], acc[2], acc[3]);
                yp[1] = make_float4(acc[4], acc[5], acc[6], acc[7]);
            }
        } else {
            int j = tid - 96;
            #pragma unroll
            for (int k = 0; k < 4; k++) {
                int fi = j + k * 32;
                int row = fi >> 4, cg = fi & 15;
                size_t g = (size_t)(r0 + row) * H + c0 + 4 * cg;
                float4 a = __ldcs(reinterpret_cast<const float4*>(x_tt + g));
                float4 b = __ldcs(reinterpret_cast<const float4*>(x_t + g));
                __stcs(reinterpret_cast<float4*>(out + g), a);
                __stcs(reinterpret_cast<float4*>(out + HH + g), b);
                __stcs(reinterpret_cast<float4*>(out + 3 * (size_t)HH + g), a);
                __stcs(reinterpret_cast<float4*>(out + 4 * (size_t)HH + g), b);
            }
        }
        __syncthreads();

        // ==== epilogue: planes 2, 5, 6 ====
        const int r = r0 + ty;
        const int cb = c0 + 4 * tx;

        float4 xtC  = *reinterpret_cast<const float4*>(s_xt  + (ty + 2) * IN_W + 4 * tx + 4);
        float4 xtU  = *reinterpret_cast<const float4*>(s_xt  + (ty + 1) * IN_W + 4 * tx + 4);
        float4 xtD  = *reinterpret_cast<const float4*>(s_xt  + (ty + 3) * IN_W + 4 * tx + 4);
        float  xtL  = s_xt[(ty + 2) * IN_W + 4 * tx + 3];
        float  xtR  = s_xt[(ty + 2) * IN_W + 4 * tx + 8];
        float4 xttC = *reinterpret_cast<const float4*>(s_xtt + (ty + 2) * IN_W + 4 * tx + 4);
        float4 spC  = *reinterpret_cast<const float4*>(s_sp  + (ty + 2) * IN_W + 4 * tx + 4);

        float4 yCv = *reinterpret_cast<const float4*>(s_y + (ty + 1) * YW + 4 * tx + 4);
        float4 yUv = *reinterpret_cast<const float4*>(s_y + (ty    ) * YW + 4 * tx + 4);
        float4 yDv = *reinterpret_cast<const float4*>(s_y + (ty + 2) * YW + 4 * tx + 4);
        float  yC0 = s_y[(ty + 1) * YW + 4 * tx + 3];
        float  yCl = s_y[(ty + 1) * YW + 4 * tx + 2];
        float  yU0 = s_y[(ty    ) * YW + 4 * tx + 3];
        float  yD0 = s_y[(ty + 2) * YW + 4 * tx + 3];

        float yc_[4] = {yC0, yCv.x, yCv.y, yCv.z};
        float yu_[4] = {yU0, yUv.x, yUv.y, yUv.z};
        float yd_[4] = {yD0, yDv.x, yDv.y, yDv.z};

        float xtc[4]  = {xtC.x, xtC.y, xtC.z, xtC.w};
        float xtu[4]  = {xtU.x, xtU.y, xtU.z, xtU.w};
        float xtd[4]  = {xtD.x, xtD.y, xtD.z, xtD.w};
        float xttc[4] = {xttC.x, xttC.y, xttC.z, xttC.w};
        float spc[4]  = {spC.x, spC.y, spC.z, spC.w};

        float x7v[4], x7p[4], xt4[4];
        #pragma unroll
        for (int j = 0; j < 4; j++) {
            int c = cb + j;
            float xl = (j == 0) ? xtL : xtc[j - 1];
            float xr = (j == 3) ? xtR : xtc[j + 1];
            float ycn = yc_[j];
            float yl  = (j == 0) ? yCl : yc_[j - 1];
            float yr2 = (j == 3) ? yCv.w : yc_[j + 1];

            float coef = spc[j] * spc[j] * 0.0025f;    // (DT/DX)^2
            float base = 2.f * xtc[j] - xttc[j];
            bool interior = (r > 0) & (r < H - 1) & (c > 0) & (c < H - 1);

            float lap = xtu[j] + xtd[j] + xl + xr - 4.f * xtc[j];
            xt4[j] = interior ? (base + lap * coef) : 0.f;

            float lapy = yu_[j] + yd_[j] + yl + yr2 - 4.f * ycn;
            float p = interior ? (base + lapy * coef) : ycn;
            x7p[j] = p;

            float v = p;
            if (r == 0) v = 0.f;
            if (c == 0)     v = xtc[j] - 0.05f * spc[j] * (xtc[j] - xr);   // DT/DX
            if (r >= 1 && r <= H - 2 && c == H - r)
                v = s_xt[(ty + 1) * IN_W + 4 * tx + j + 3];                // xt[r-1,c-1]
            if (c == H - 1) v = xtc[j] - 0.05f * spc[j] * (xtc[j] - xl);
            if (r == H - 1) v = 0.f;
            x7v[j] = v;
        }

        size_t g = (size_t)r * H + cb;
        __stcs(reinterpret_cast<float4*>(out + 2 * (size_t)HH + g),
               *reinterpret_cast<float4*>(x7v));
        __stcs(reinterpret_cast<float4*>(out + 5 * (size_t)HH + g),
               *reinterpret_cast<float4*>(x7p));
        __stcs(reinterpret_cast<float4*>(out + 6 * (size_t)HH + g),
               *reinterpret_cast<float4*>(xt4));

        __syncthreads();   // epilogue reads done before next stage overwrites buf[pb]

        // folded observation scatter for this tile (ordered after x7 stores)
        #pragma unroll
        for (int i = tid; i < 256; i += 128) {
            if (i < P) {
                int lx = loc_x[i];
                if (lx != -1) {
                    int lyv = loc_y[i];
                    if (lx >= r0 && lx < r0 + TH && lyv >= c0 && lyv < c0 + TW) {
                        int id = dscalar(p_id, 1);
                        size_t obs_off = (size_t)(id * bsize + step + 2) * HH;
                        size_t gs = (size_t)lx * H + lyv;
                        out[2 * (size_t)HH + gs] = ref_sol[obs_off + gs];
                    }
                }
            }
        }
        pb ^= 1;
    }
}

extern "C" void kernel_launch(void* const* d_in, const int* in_sizes, int n_in,
                              void* d_out, int out_size)
{
    const float* ref_speed = (const float*)d_in[0];
    const float* batch     = (const float*)d_in[1];
    const float* x_tt      = (const float*)d_in[2];
    const float* x_t       = (const float*)d_in[3];
    const float* ref_sol   = (const float*)d_in[4];
    const float* conv_v    = (const float*)d_in[5];
    const float* conv_g    = (const float*)d_in[6];
    const float* conv_b    = (const float*)d_in[7];
    const int*   loc_x     = (const int*)d_in[8];
    const int*   loc_y     = (const int*)d_in[9];
    const int* p_bsize    = (n_in > 10) ? (const int*)d_in[10] : nullptr;
    const int* p_id       = (n_in > 11) ? (const int*)d_in[11] : nullptr;
    const int* p_flag     = (n_in > 12) ? (const int*)d_in[12] : nullptr;
    const int* p_flag_num = (n_in > 13) ? (const int*)d_in[13] : nullptr;

    float* out = (float*)d_out;
    int P = in_sizes[8];

    pgonet_main<<<GRID, 128>>>(ref_speed, batch, x_tt, x_t,
                               conv_v, conv_g, conv_b,
                               ref_sol, loc_x, loc_y,
                               p_bsize, p_id, p_flag, p_flag_num,
                               out, P);
}

// round 15
// speedup vs baseline: 1.4929x; 1.4929x over previous
#include <cuda_runtime.h>
#include <math.h>
#include <stdint.h>

#define H 2048
#define HH (H*H)
#define TW 64                  // tile width (cols)
#define TH 8                   // tile height (rows)
#define IN_W 76                // input smem stride: cols c0-4 .. c0+71 (19 float4)
#define IN_H 12                // rows r0-2 .. r0+9
#define IN_HW (IN_H * IN_W)
#define YW 72                  // y smem stride: sc = (gy-c0) + 3
#define YH 10                  // y rows: gyr = r0-1+ly, ly 0..9

__device__ __forceinline__ int dscalar(const int* p, int def) {
    return p ? p[0] : def;
}

__device__ __forceinline__ void cp_async16(uint32_t dst_smem, const void* src, int src_bytes) {
    asm volatile("cp.async.cg.shared.global [%0], [%1], 16, %2;\n"
                 :: "r"(dst_smem), "l"(src), "r"(src_bytes));
}
__device__ __forceinline__ void cp_async_commit_wait() {
    asm volatile("cp.async.commit_group;\n");
    asm volatile("cp.async.wait_group 0;\n" ::: "memory");
}

__global__ __launch_bounds__(128, 12)
void pgonet_main(const float* __restrict__ ref_speed,
                 const float* __restrict__ batch,
                 const float* __restrict__ x_tt,
                 const float* __restrict__ x_t,
                 const float* __restrict__ conv_v,
                 const float* __restrict__ conv_g,
                 const float* __restrict__ conv_b,
                 const float* __restrict__ ref_sol,
                 const int*   __restrict__ loc_x,
                 const int*   __restrict__ loc_y,
                 const int* p_bsize, const int* p_id,
                 const int* p_flag, const int* p_flag_num,
                 float* __restrict__ out, int P)
{
    __shared__ float s_in[3 * IN_HW];   // ch0=xtt ch1=xt ch2=speed
    __shared__ float s_y[YH * YW];
    __shared__ float4 s_W4[9];          // (w0,w1,w2,0) per (ch,kh)
    __shared__ float s_b;

    const int tx = threadIdx.x & 15;      // 0..15 (float4 col group)
    const int ty = threadIdx.x >> 4;      // 0..7  (row)
    const int tid = threadIdx.x;
    const int r0 = blockIdx.y * TH;
    const int c0 = blockIdx.x * TW;

    const int bsize = dscalar(p_bsize, 10);
    const int ntb   = dscalar(p_flag, 1) - 1;
    const int step  = dscalar(p_flag_num, 1) - 1;
    const int i0    = ntb * bsize + step;
    const float* __restrict__ xtt_g = batch + (size_t)i0 * HH;
    const float* __restrict__ xt_g  = batch + (size_t)(i0 + 1) * HH;

    // ---- async-stage 3 x 12 x 19 float4 = 684 groups over 128 threads ----
    uint32_t s_in_u32;
    {
        uint32_t a;
        asm("{ .reg .u64 t; cvta.to.shared.u64 t, %1; cvt.u32.u64 %0, t; }"
            : "=r"(a) : "l"(s_in));
        s_in_u32 = a;
    }
    #pragma unroll
    for (int it = 0; it < 6; it++) {
        int idx = tid + it * 128;
        if (idx < 3 * IN_H * 19) {
            int ch = idx / (IN_H * 19);
            int k  = idx - ch * (IN_H * 19);
            int lr = k / 19, lq = k - lr * 19;
            int gr = r0 - 2 + lr;
            int gc = c0 - 4 + 4 * lq;
            bool ok = (gr >= 0) && (gr < H) && (gc >= 0) && (gc + 3 < H);
            const float* p = (ch == 0) ? xtt_g : ((ch == 1) ? xt_g : ref_speed);
            const float* src = p + (ok ? ((size_t)gr * H + gc) : 0);
            uint32_t dst = s_in_u32 + 4u * (ch * IN_HW + lr * IN_W + 4 * lq);
            cp_async16(dst, src, ok ? 16 : 0);
        }
    }

    // ---- planes 0,1,3,4 copies: exactly 1 float4 unit per thread.
    // Independent of staged smem — overlaps the cp.async DRAM fill.
    {
        size_t g = (size_t)(r0 + ty) * H + c0 + 4 * tx;
        float4 a = __ldcs(reinterpret_cast<const float4*>(x_tt + g));
        float4 b = __ldcs(reinterpret_cast<const float4*>(x_t + g));
        __stcs(reinterpret_cast<float4*>(out + g), a);
        __stcs(reinterpret_cast<float4*>(out + HH + g), b);
        __stcs(reinterpret_cast<float4*>(out + 3 * (size_t)HH + g), a);
        __stcs(reinterpret_cast<float4*>(out + 4 * (size_t)HH + g), b);
    }

    if (tid == 0) {
        float ss = 0.f;
        #pragma unroll
        for (int i = 0; i < 27; i++) { float v = conv_v[i]; ss += v * v; }
        float scale = conv_g[0] / sqrtf(ss);
        #pragma unroll
        for (int i = 0; i < 9; i++)
            s_W4[i] = make_float4(conv_v[3 * i] * scale,
                                  conv_v[3 * i + 1] * scale,
                                  conv_v[3 * i + 2] * scale, 0.f);
        s_b = conv_b[0];
    }

    cp_async_commit_wait();
    __syncthreads();

    const float* s_xtt = s_in;
    const float* s_xt  = s_in + IN_HW;
    const float* s_sp  = s_in + 2 * IN_HW;

    // ==== phase B: pure conv — 90 strips on threads 0..89 ====
    if (tid < YH * 9) {
        const float bconv = s_b;
        int ly = tid / 9, q = tid - ly * 9;
        float acc[8];
        #pragma unroll
        for (int k = 0; k < 8; k++) acc[k] = bconv;
        #pragma unroll
        for (int ch = 0; ch < 3; ch++) {
            #pragma unroll
            for (int kh = 0; kh < 3; kh++) {
                const float4* rp = reinterpret_cast<const float4*>(
                    s_in + ch * IN_HW + (ly + kh) * IN_W + 8 * q);
                float4 A = rp[0], B = rp[1], C = rp[2];
                float t[12] = {A.x, A.y, A.z, A.w, B.x, B.y, B.z, B.w,
                               C.x, C.y, C.z, C.w};
                float4 w = s_W4[ch * 3 + kh];
                #pragma unroll
                for (int k = 0; k < 8; k++) {
                    acc[k] = fmaf(w.x, t[k], acc[k]);
                    acc[k] = fmaf(w.y, t[k + 1], acc[k]);
                    acc[k] = fmaf(w.z, t[k + 2], acc[k]);
                }
            }
        }
        float4* yp = reinterpret_cast<float4*>(s_y + ly * YW + 8 * q);
        yp[0] = make_float4(acc[0], acc[1], acc[2], acc[3]);
        yp[1] = make_float4(acc[4], acc[5], acc[6], acc[7]);
    }
    __syncthreads();

    // ==== epilogue: planes 2, 5, 6 — all 128 threads, 4 px each ====
    const int r = r0 + ty;
    const int cb = c0 + 4 * tx;

    float4 xtC  = *reinterpret_cast<const float4*>(s_xt  + (ty + 2) * IN_W + 4 * tx + 4);
    float4 xtU  = *reinterpret_cast<const float4*>(s_xt  + (ty + 1) * IN_W + 4 * tx + 4);
    float4 xtD  = *reinterpret_cast<const float4*>(s_xt  + (ty + 3) * IN_W + 4 * tx + 4);
    float  xtL  = s_xt[(ty + 2) * IN_W + 4 * tx + 3];
    float  xtR  = s_xt[(ty + 2) * IN_W + 4 * tx + 8];
    float4 xttC = *reinterpret_cast<const float4*>(s_xtt + (ty + 2) * IN_W + 4 * tx + 4);
    float4 spC  = *reinterpret_cast<const float4*>(s_sp  + (ty + 2) * IN_W + 4 * tx + 4);

    float4 yCv = *reinterpret_cast<const float4*>(s_y + (ty + 1) * YW + 4 * tx + 4);
    float4 yUv = *reinterpret_cast<const float4*>(s_y + (ty    ) * YW + 4 * tx + 4);
    float4 yDv = *reinterpret_cast<const float4*>(s_y + (ty + 2) * YW + 4 * tx + 4);
    float  yC0 = s_y[(ty + 1) * YW + 4 * tx + 3];
    float  yCl = s_y[(ty + 1) * YW + 4 * tx + 2];
    float  yU0 = s_y[(ty    ) * YW + 4 * tx + 3];
    float  yD0 = s_y[(ty + 2) * YW + 4 * tx + 3];

    float yc_[4] = {yC0, yCv.x, yCv.y, yCv.z};
    float yu_[4] = {yU0, yUv.x, yUv.y, yUv.z};
    float yd_[4] = {yD0, yDv.x, yDv.y, yDv.z};

    float xtc[4]  = {xtC.x, xtC.y, xtC.z, xtC.w};
    float xtu[4]  = {xtU.x, xtU.y, xtU.z, xtU.w};
    float xtd[4]  = {xtD.x, xtD.y, xtD.z, xtD.w};
    float xttc[4] = {xttC.x, xttC.y, xttC.z, xttC.w};
    float spc[4]  = {spC.x, spC.y, spC.z, spC.w};

    float x7v[4], x7p[4], xt4[4];
    #pragma unroll
    for (int j = 0; j < 4; j++) {
        int c = cb + j;
        float xl = (j == 0) ? xtL : xtc[j - 1];
        float xr = (j == 3) ? xtR : xtc[j + 1];
        float ycn = yc_[j];
        float yl  = (j == 0) ? yCl : yc_[j - 1];
        float yr2 = (j == 3) ? yCv.w : yc_[j + 1];

        float coef = spc[j] * spc[j] * 0.0025f;    // (DT/DX)^2
        float base = 2.f * xtc[j] - xttc[j];
        bool interior = (r > 0) & (r < H - 1) & (c > 0) & (c < H - 1);

        float lap = xtu[j] + xtd[j] + xl + xr - 4.f * xtc[j];
        xt4[j] = interior ? (base + lap * coef) : 0.f;

        float lapy = yu_[j] + yd_[j] + yl + yr2 - 4.f * ycn;
        float p = interior ? (base + lapy * coef) : ycn;
        x7p[j] = p;

        float v = p;
        if (r == 0) v = 0.f;
        if (c == 0)     v = xtc[j] - 0.05f * spc[j] * (xtc[j] - xr);   // DT/DX
        if (r >= 1 && r <= H - 2 && c == H - r)
            v = s_xt[(ty + 1) * IN_W + 4 * tx + j + 3];                // xt[r-1,c-1]
        if (c == H - 1) v = xtc[j] - 0.05f * spc[j] * (xtc[j] - xl);
        if (r == H - 1) v = 0.f;
        x7v[j] = v;
    }

    size_t g = (size_t)r * H + cb;
    __stcs(reinterpret_cast<float4*>(out + 2 * (size_t)HH + g),
           *reinterpret_cast<float4*>(x7v));
    __stcs(reinterpret_cast<float4*>(out + 5 * (size_t)HH + g),
           *reinterpret_cast<float4*>(x7p));
    __stcs(reinterpret_cast<float4*>(out + 6 * (size_t)HH + g),
           *reinterpret_cast<float4*>(xt4));

    // ---- folded observation scatter (block owning pixel overrides plane 2) ----
    __syncthreads();
    for (int i = tid; i < P; i += 128) {
        int lx = loc_x[i];
        if (lx != -1) {
            int lyv = loc_y[i];
            if (lx >= r0 && lx < r0 + TH && lyv >= c0 && lyv < c0 + TW) {
                int id = dscalar(p_id, 1);
                size_t obs_off = (size_t)(id * bsize + step + 2) * HH;
                size_t gs = (size_t)lx * H + lyv;
                out[2 * (size_t)HH + gs] = ref_sol[obs_off + gs];
            }
        }
    }
}

extern "C" void kernel_launch(void* const* d_in, const int* in_sizes, int n_in,
                              void* d_out, int out_size)
{
    const float* ref_speed = (const float*)d_in[0];
    const float* batch     = (const float*)d_in[1];
    const float* x_tt      = (const float*)d_in[2];
    const float* x_t       = (const float*)d_in[3];
    const float* ref_sol   = (const float*)d_in[4];
    const float* conv_v    = (const float*)d_in[5];
    const float* conv_g    = (const float*)d_in[6];
    const float* conv_b    = (const float*)d_in[7];
    const int*   loc_x     = (const int*)d_in[8];
    const int*   loc_y     = (const int*)d_in[9];
    const int* p_bsize    = (n_in > 10) ? (const int*)d_in[10] : nullptr;
    const int* p_id       = (n_in > 11) ? (const int*)d_in[11] : nullptr;
    const int* p_flag     = (n_in > 12) ? (const int*)d_in[12] : nullptr;
    const int* p_flag_num = (n_in > 13) ? (const int*)d_in[13] : nullptr;

    float* out = (float*)d_out;
    int P = in_sizes[8];

    dim3 block(128);
    dim3 grid(H / TW, H / TH);
    pgonet_main<<<grid, block>>>(ref_speed, batch, x_tt, x_t,
                                 conv_v, conv_g, conv_b,
                                 ref_sol, loc_x, loc_y,
                                 p_bsize, p_id, p_flag, p_flag_num,
                                 out, P);
}

// round 16
// speedup vs baseline: 1.5453x; 1.0351x over previous
#include <cuda_runtime.h>
#include <math.h>
#include <stdint.h>

#define H 2048
#define HH (H*H)
#define TW 64                  // tile width (cols)
#define TH 8                   // tile height (rows)
#define IN_W 76                // input smem stride: cols c0-4 .. c0+71 (19 float4)
#define IN_H 12                // rows r0-2 .. r0+9
#define IN_HW (IN_H * IN_W)
#define YW 72                  // y smem stride: sc = (gy-c0) + 3
#define YH 10                  // y rows: gyr = r0-1+ly, ly 0..9

__device__ __forceinline__ int dscalar(const int* p, int def) {
    return p ? p[0] : def;
}

__device__ __forceinline__ void cp_async16(uint32_t dst_smem, const void* src, int src_bytes) {
    asm volatile("cp.async.cg.shared.global [%0], [%1], 16, %2;\n"
                 :: "r"(dst_smem), "l"(src), "r"(src_bytes));
}
__device__ __forceinline__ void cp_async_commit_wait() {
    asm volatile("cp.async.commit_group;\n");
    asm volatile("cp.async.wait_group 0;\n" ::: "memory");
}

__global__ __launch_bounds__(128, 12)
void pgonet_main(const float* __restrict__ ref_speed,
                 const float* __restrict__ batch,
                 const float* __restrict__ x_tt,
                 const float* __restrict__ x_t,
                 const float* __restrict__ conv_v,
                 const float* __restrict__ conv_g,
                 const float* __restrict__ conv_b,
                 const float* __restrict__ ref_sol,
                 const int*   __restrict__ loc_x,
                 const int*   __restrict__ loc_y,
                 const int* p_bsize, const int* p_id,
                 const int* p_flag, const int* p_flag_num,
                 float* __restrict__ out, int P)
{
    __shared__ float s_in[3 * IN_HW];   // ch0=xtt ch1=xt ch2=speed
    __shared__ float s_y[YH * YW];
    __shared__ float4 s_W4[9];          // (w0,w1,w2,0) per (ch,kh)
    __shared__ float s_b;
    __shared__ int s_nmatch;
    __shared__ int s_match[256];

    const int tx = threadIdx.x & 15;      // 0..15 (float4 col group)
    const int ty = threadIdx.x >> 4;      // 0..7  (row)
    const int tid = threadIdx.x;
    const int r0 = blockIdx.y * TH;
    const int c0 = blockIdx.x * TW;

    const int bsize = dscalar(p_bsize, 10);
    const int ntb   = dscalar(p_flag, 1) - 1;
    const int step  = dscalar(p_flag_num, 1) - 1;
    const int i0    = ntb * bsize + step;
    const float* __restrict__ xtt_g = batch + (size_t)i0 * HH;
    const float* __restrict__ xt_g  = batch + (size_t)(i0 + 1) * HH;

    // ---- async-stage 3 x 12 x 19 float4 = 684 groups over 128 threads ----
    uint32_t s_in_u32;
    {
        uint32_t a;
        asm("{ .reg .u64 t; cvta.to.shared.u64 t, %1; cvt.u32.u64 %0, t; }"
            : "=r"(a) : "l"(s_in));
        s_in_u32 = a;
    }
    #pragma unroll
    for (int it = 0; it < 6; it++) {
        int idx = tid + it * 128;
        if (idx < 3 * IN_H * 19) {
            int ch = idx / (IN_H * 19);
            int k  = idx - ch * (IN_H * 19);
            int lr = k / 19, lq = k - lr * 19;
            int gr = r0 - 2 + lr;
            int gc = c0 - 4 + 4 * lq;
            bool ok = (gr >= 0) && (gr < H) && (gc >= 0) && (gc + 3 < H);
            const float* p = (ch == 0) ? xtt_g : ((ch == 1) ? xt_g : ref_speed);
            const float* src = p + (ok ? ((size_t)gr * H + gc) : 0);
            uint32_t dst = s_in_u32 + 4u * (ch * IN_HW + lr * IN_W + 4 * lq);
            cp_async16(dst, src, ok ? 16 : 0);
        }
    }

    // ---- planes 0,1,3,4 copies: exactly 1 float4 unit per thread.
    // Independent of staged smem — overlaps the cp.async DRAM fill.
    {
        size_t g = (size_t)(r0 + ty) * H + c0 + 4 * tx;
        float4 a = __ldcs(reinterpret_cast<const float4*>(x_tt + g));
        float4 b = __ldcs(reinterpret_cast<const float4*>(x_t + g));
        __stcs(reinterpret_cast<float4*>(out + g), a);
        __stcs(reinterpret_cast<float4*>(out + HH + g), b);
        __stcs(reinterpret_cast<float4*>(out + 3 * (size_t)HH + g), a);
        __stcs(reinterpret_cast<float4*>(out + 4 * (size_t)HH + g), b);
    }

    if (tid == 0) {
        s_nmatch = 0;
        float ss = 0.f;
        #pragma unroll
        for (int i = 0; i < 27; i++) { float v = conv_v[i]; ss += v * v; }
        float scale = conv_g[0] / sqrtf(ss);
        #pragma unroll
        for (int i = 0; i < 9; i++)
            s_W4[i] = make_float4(conv_v[3 * i] * scale,
                                  conv_v[3 * i + 1] * scale,
                                  conv_v[3 * i + 2] * scale, 0.f);
        s_b = conv_b[0];
    }

    cp_async_commit_wait();
    __syncthreads();

    const float* s_xtt = s_in;
    const float* s_xt  = s_in + IN_HW;
    const float* s_sp  = s_in + 2 * IN_HW;

    // ==== phase B: conv (90 strips, threads 0..89); scatter scan (96..127) ====
    if (tid < YH * 9) {
        const float bconv = s_b;
        int ly = tid / 9, q = tid - ly * 9;
        float acc[8];
        #pragma unroll
        for (int k = 0; k < 8; k++) acc[k] = bconv;
        #pragma unroll
        for (int ch = 0; ch < 3; ch++) {
            #pragma unroll
            for (int kh = 0; kh < 3; kh++) {
                const float4* rp = reinterpret_cast<const float4*>(
                    s_in + ch * IN_HW + (ly + kh) * IN_W + 8 * q);
                float4 A = rp[0], B = rp[1], C = rp[2];
                float t[12] = {A.x, A.y, A.z, A.w, B.x, B.y, B.z, B.w,
                               C.x, C.y, C.z, C.w};
                float4 w = s_W4[ch * 3 + kh];
                #pragma unroll
                for (int k = 0; k < 8; k++) {
                    acc[k] = fmaf(w.x, t[k], acc[k]);
                    acc[k] = fmaf(w.y, t[k + 1], acc[k]);
                    acc[k] = fmaf(w.z, t[k + 2], acc[k]);
                }
            }
        }
        float4* yp = reinterpret_cast<float4*>(s_y + ly * YW + 8 * q);
        yp[0] = make_float4(acc[0], acc[1], acc[2], acc[3]);
        yp[1] = make_float4(acc[4], acc[5], acc[6], acc[7]);
    } else if (tid >= 96) {
        // scan observation points for in-tile matches (overlaps conv)
        for (int i = tid - 96; i < P; i += 32) {
            int lx = loc_x[i];
            if (lx >= r0 && lx < r0 + TH) {
                int lyv = loc_y[i];
                if (lyv >= c0 && lyv < c0 + TW) {   // lx != -1 implied by range
                    int slot = atomicAdd(&s_nmatch, 1);
                    if (slot < 256) s_match[slot] = i;
                }
            }
        }
    }
    __syncthreads();

    // ==== epilogue: planes 2, 5, 6 — all 128 threads, 4 px each ====
    const int r = r0 + ty;
    const int cb = c0 + 4 * tx;

    float4 xtC  = *reinterpret_cast<const float4*>(s_xt  + (ty + 2) * IN_W + 4 * tx + 4);
    float4 xtU  = *reinterpret_cast<const float4*>(s_xt  + (ty + 1) * IN_W + 4 * tx + 4);
    float4 xtD  = *reinterpret_cast<const float4*>(s_xt  + (ty + 3) * IN_W + 4 * tx + 4);
    float  xtL  = s_xt[(ty + 2) * IN_W + 4 * tx + 3];
    float  xtR  = s_xt[(ty + 2) * IN_W + 4 * tx + 8];
    float4 xttC = *reinterpret_cast<const float4*>(s_xtt + (ty + 2) * IN_W + 4 * tx + 4);
    float4 spC  = *reinterpret_cast<const float4*>(s_sp  + (ty + 2) * IN_W + 4 * tx + 4);

    float4 yCv = *reinterpret_cast<const float4*>(s_y + (ty + 1) * YW + 4 * tx + 4);
    float4 yUv = *reinterpret_cast<const float4*>(s_y + (ty    ) * YW + 4 * tx + 4);
    float4 yDv = *reinterpret_cast<const float4*>(s_y + (ty + 2) * YW + 4 * tx + 4);
    float  yC0 = s_y[(ty + 1) * YW + 4 * tx + 3];
    float  yCl = s_y[(ty + 1) * YW + 4 * tx + 2];
    float  yU0 = s_y[(ty    ) * YW + 4 * tx + 3];
    float  yD0 = s_y[(ty + 2) * YW + 4 * tx + 3];

    float yc_[4] = {yC0, yCv.x, yCv.y, yCv.z};
    float yu_[4] = {yU0, yUv.x, yUv.y, yUv.z};
    float yd_[4] = {yD0, yDv.x, yDv.y, yDv.z};

    float xtc[4]  = {xtC.x, xtC.y, xtC.z, xtC.w};
    float xtu[4]  = {xtU.x, xtU.y, xtU.z, xtU.w};
    float xtd[4]  = {xtD.x, xtD.y, xtD.z, xtD.w};
    float xttc[4] = {xttC.x, xttC.y, xttC.z, xttC.w};
    float spc[4]  = {spC.x, spC.y, spC.z, spC.w};

    float x7v[4], x7p[4], xt4[4];
    #pragma unroll
    for (int j = 0; j < 4; j++) {
        int c = cb + j;
        float xl = (j == 0) ? xtL : xtc[j - 1];
        float xr = (j == 3) ? xtR : xtc[j + 1];
        float ycn = yc_[j];
        float yl  = (j == 0) ? yCl : yc_[j - 1];
        float yr2 = (j == 3) ? yCv.w : yc_[j + 1];

        float coef = spc[j] * spc[j] * 0.0025f;    // (DT/DX)^2
        float base = 2.f * xtc[j] - xttc[j];
        bool interior = (r > 0) & (r < H - 1) & (c > 0) & (c < H - 1);

        float lap = xtu[j] + xtd[j] + xl + xr - 4.f * xtc[j];
        xt4[j] = interior ? (base + lap * coef) : 0.f;

        float lapy = yu_[j] + yd_[j] + yl + yr2 - 4.f * ycn;
        float p = interior ? (base + lapy * coef) : ycn;
        x7p[j] = p;

        float v = p;
        if (r == 0) v = 0.f;
        if (c == 0)     v = xtc[j] - 0.05f * spc[j] * (xtc[j] - xr);   // DT/DX
        if (r >= 1 && r <= H - 2 && c == H - r)
            v = s_xt[(ty + 1) * IN_W + 4 * tx + j + 3];                // xt[r-1,c-1]
        if (c == H - 1) v = xtc[j] - 0.05f * spc[j] * (xtc[j] - xl);
        if (r == H - 1) v = 0.f;
        x7v[j] = v;
    }

    size_t g = (size_t)r * H + cb;
    __stcs(reinterpret_cast<float4*>(out + 2 * (size_t)HH + g),
           *reinterpret_cast<float4*>(x7v));
    __stcs(reinterpret_cast<float4*>(out + 5 * (size_t)HH + g),
           *reinterpret_cast<float4*>(x7p));
    __stcs(reinterpret_cast<float4*>(out + 6 * (size_t)HH + g),
           *reinterpret_cast<float4*>(xt4));

    // ---- observation override (rare): s_nmatch is CTA-uniform (written in
    // phase B, ordered by the barrier above), so the conditional barrier is safe.
    if (s_nmatch > 0) {
        __syncthreads();   // order plane-2 STGs above before overrides
        int nm = s_nmatch < 256 ? s_nmatch : 256;
        int id = dscalar(p_id, 1);
        size_t obs_off = (size_t)(id * bsize + step + 2) * HH;
        for (int m = tid; m < nm; m += 128) {
            int i = s_match[m];
            size_t gs = (size_t)loc_x[i] * H + loc_y[i];
            out[2 * (size_t)HH + gs] = ref_sol[obs_off + gs];
        }
    }
}

extern "C" void kernel_launch(void* const* d_in, const int* in_sizes, int n_in,
                              void* d_out, int out_size)
{
    const float* ref_speed = (const float*)d_in[0];
    const float* batch     = (const float*)d_in[1];
    const float* x_tt      = (const float*)d_in[2];
    const float* x_t       = (const float*)d_in[3];
    const float* ref_sol   = (const float*)d_in[4];
    const float* conv_v    = (const float*)d_in[5];
    const float* conv_g    = (const float*)d_in[6];
    const float* conv_b    = (const float*)d_in[7];
    const int*   loc_x     = (const int*)d_in[8];
    const int*   loc_y     = (const int*)d_in[9];
    const int* p_bsize    = (n_in > 10) ? (const int*)d_in[10] : nullptr;
    const int* p_id       = (n_in > 11) ? (const int*)d_in[11] : nullptr;
    const int* p_flag     = (n_in > 12) ? (const int*)d_in[12] : nullptr;
    const int* p_flag_num = (n_in > 13) ? (const int*)d_in[13] : nullptr;

    float* out = (float*)d_out;
    int P = in_sizes[8];

    dim3 block(128);
    dim3 grid(H / TW, H / TH);
    pgonet_main<<<grid, block>>>(ref_speed, batch, x_tt, x_t,
                                 conv_v, conv_g, conv_b,
                                 ref_sol, loc_x, loc_y,
                                 p_bsize, p_id, p_flag, p_flag_num,
                                 out, P);
}